// round 15
// baseline (speedup 1.0000x reference)
#include <cuda_runtime.h>
#include <cuda_fp16.h>
#include <math.h>
#include <stdint.h>

#define LSTEPS 64
#define BDIM   512
#define HDIM   1024
#define SDIM   128
#define ADIM   32
#define NDIM   1024
#define EDIM   1024

#define BH ((size_t)BDIM * HDIM)
#define BS ((size_t)BDIM * SDIM)
#define LBH ((size_t)LSTEPS * BH)
#define LBS ((size_t)LSTEPS * BS)
#define LACT (LSTEPS * BDIM * ADIM)
#define LOBS ((size_t)LSTEPS * BDIM * EDIM)

typedef __half half_t;

// ---------------- scratch: fp32 ---------------------------------------------
__device__ __align__(16) float g_gi[BDIM * 3 * HDIM];
__device__ __align__(16) float g_gh[BDIM * 3 * HDIM];
__device__ __align__(16) float g_qp[LOBS];            // qe obs-partial (+b_eq)
__device__ unsigned int g_cnt[LSTEPS];                // per-step grid-barrier counters

// ---------------- scratch: fp16 hi/lo activations ---------------------------
__device__ __align__(16) half_t g_x_h [BDIM * HDIM], g_x_l [BDIM * HDIM];
__device__ __align__(16) half_t g_h_h [BDIM * HDIM], g_h_l [BDIM * HDIM];
__device__ __align__(16) half_t g_pe_h[BDIM * NDIM], g_pe_l[BDIM * NDIM];
__device__ __align__(16) half_t g_qe_h[BDIM * NDIM], g_qe_l[BDIM * NDIM];
__device__ __align__(16) half_t g_sp_h[BDIM * SDIM], g_sp_l[BDIM * SDIM];
__device__ __align__(16) half_t g_act_h[LACT], g_act_l[LACT];
__device__ __align__(16) half_t g_ob_h[LOBS], g_ob_l[LOBS];

// ---------------- scratch: converted weights (fp16) -------------------------
#define SZ_WSA (HDIM * (SDIM + ADIM))
#define SZ_WIH (3 * HDIM * HDIM)
#define SZ_WEP (NDIM * HDIM)
#define SZ_WPR (2 * SDIM * NDIM)

__device__ __align__(16) half_t g_Wsa[SZ_WSA];
__device__ __align__(16) half_t g_Wih[SZ_WIH];
__device__ __align__(16) half_t g_Whh[SZ_WIH];
__device__ __align__(16) half_t g_Wpq[2 * NDIM * HDIM];   // [Wep; Weq[:, :1024]]
__device__ __align__(16) half_t g_Wq2[NDIM * EDIM];       // Weq[:, 1024:]
__device__ __align__(16) half_t g_Wpr[SZ_WPR];            // row-interleaved mean/std
__device__ __align__(16) half_t g_Wpo[SZ_WPR];

// ------------------------------- helpers ------------------------------------
__device__ __forceinline__ float sigmoidf_(float x) { return 1.0f / (1.0f + __expf(-x)); }
__device__ __forceinline__ float tanhf_(float x)    { return 1.0f - 2.0f / (__expf(2.0f * x) + 1.0f); }
__device__ __forceinline__ float softplusf_(float x) {
    return fmaxf(x, 0.0f) + log1pf(__expf(-fabsf(x)));
}
__device__ __forceinline__ uint32_t pack_h2(half_t a, half_t b) {
    __half2 t(a, b);
    return *reinterpret_cast<uint32_t*>(&t);
}
__device__ __forceinline__ void split_h(float v, half_t& h, half_t& l) {
    h = __float2half_rn(v);
    l = __float2half_rn(v - __half2float(h));
}
__device__ __forceinline__ void split_store4(float4 v, half_t* hdst, half_t* ldst, size_t idx4) {
    half_t h0, h1, h2, h3, l0, l1, l2, l3;
    split_h(v.x, h0, l0); split_h(v.y, h1, l1);
    split_h(v.z, h2, l2); split_h(v.w, h3, l3);
    reinterpret_cast<uint2*>(hdst)[idx4] = make_uint2(pack_h2(h0, h1), pack_h2(h2, h3));
    reinterpret_cast<uint2*>(ldst)[idx4] = make_uint2(pack_h2(l0, l1), pack_h2(l2, l3));
}
__device__ __forceinline__ uint2 conv4(float4 v) {
    return make_uint2(pack_h2(__float2half_rn(v.x), __float2half_rn(v.y)),
                      pack_h2(__float2half_rn(v.z), __float2half_rn(v.w)));
}
__device__ __forceinline__ void ldsm4(uint32_t* r, uint32_t addr) {
    asm volatile("ldmatrix.sync.aligned.m8n8.x4.shared.b16 {%0,%1,%2,%3}, [%4];"
                 : "=r"(r[0]), "=r"(r[1]), "=r"(r[2]), "=r"(r[3]) : "r"(addr));
}
__device__ __forceinline__ void mma_f16(float* c, const uint32_t* a, uint32_t b0, uint32_t b1) {
    asm volatile("mma.sync.aligned.m16n8k16.row.col.f32.f16.f16.f32 "
                 "{%0,%1,%2,%3}, {%4,%5,%6,%7}, {%8,%9}, {%0,%1,%2,%3};"
                 : "+f"(c[0]), "+f"(c[1]), "+f"(c[2]), "+f"(c[3])
                 : "r"(a[0]), "r"(a[1]), "r"(a[2]), "r"(a[3]), "r"(b0), "r"(b1));
}
__device__ __forceinline__ void cp16(uint32_t dst, const void* src) {
    asm volatile("cp.async.cg.shared.global [%0], [%1], 16;" :: "r"(dst), "l"(src));
}
__device__ __forceinline__ void cp_commit() {
    asm volatile("cp.async.commit_group;" ::: "memory");
}
__device__ __forceinline__ void cp_wait1() {
    asm volatile("cp.async.wait_group 1;" ::: "memory");
}

// -------------------- one-shot prep (all converts, flat dispatch) -----------
#define N_OBS  ((int)(LOBS / 4))
#define N_WIH  (SZ_WIH / 4)
#define N_WSA  (SZ_WSA / 4)
#define N_WEP  (SZ_WEP / 4)
#define N_ILV  (SZ_WPR / 4)
#define N_H0   ((int)(BH / 4))
#define N_SP   ((int)(BS / 4))
#define N_ACT  (LACT / 4)
#define N_CNT  LSTEPS
#define N_TOT  (N_OBS + 2 * N_WIH + N_WSA + 3 * N_WEP + 2 * N_ILV + N_H0 + N_SP + N_ACT + N_CNT)

__global__ void prep_kernel(
    const float* __restrict__ Wih_f, const float* __restrict__ Whh_f,
    const float* __restrict__ Wsa_f, const float* __restrict__ Wep_f,
    const float* __restrict__ Weq_f, const float* __restrict__ Wpr_f,
    const float* __restrict__ Wpo_f,
    const float* __restrict__ prev_hidden, const float* __restrict__ prev_state,
    const float* __restrict__ nt0, const float* __restrict__ actions,
    const float* __restrict__ obs,
    half_t* __restrict__ Wih, half_t* __restrict__ Whh, half_t* __restrict__ Wsa,
    half_t* __restrict__ Wpq, half_t* __restrict__ Wq2,
    half_t* __restrict__ Wpr, half_t* __restrict__ Wpo,
    half_t* __restrict__ hh, half_t* __restrict__ hl,
    half_t* __restrict__ sph, half_t* __restrict__ spl,
    half_t* __restrict__ ah, half_t* __restrict__ al,
    half_t* __restrict__ oh, half_t* __restrict__ ol)
{
    int i = blockIdx.x * blockDim.x + threadIdx.x;
    if (i < N_OBS) {
        split_store4(reinterpret_cast<const float4*>(obs)[i], oh, ol, i);
        return;
    }
    i -= N_OBS;
    if (i < N_WIH) {
        reinterpret_cast<uint2*>(Wih)[i] = conv4(reinterpret_cast<const float4*>(Wih_f)[i]);
        return;
    }
    i -= N_WIH;
    if (i < N_WIH) {
        reinterpret_cast<uint2*>(Whh)[i] = conv4(reinterpret_cast<const float4*>(Whh_f)[i]);
        return;
    }
    i -= N_WIH;
    if (i < N_WSA) {
        reinterpret_cast<uint2*>(Wsa)[i] = conv4(reinterpret_cast<const float4*>(Wsa_f)[i]);
        return;
    }
    i -= N_WSA;
    if (i < N_WEP) {
        reinterpret_cast<uint2*>(Wpq)[i] = conv4(reinterpret_cast<const float4*>(Wep_f)[i]);
        return;
    }
    i -= N_WEP;
    if (i < N_WEP) {
        int n = i >> 8, k4 = i & 255;
        float4 v = *reinterpret_cast<const float4*>(Weq_f + (size_t)n * 2048 + k4 * 4);
        reinterpret_cast<uint2*>(Wpq)[N_WEP + i] = conv4(v);
        return;
    }
    i -= N_WEP;
    if (i < N_WEP) {
        int n = i >> 8, k4 = i & 255;
        float4 v = *reinterpret_cast<const float4*>(Weq_f + (size_t)n * 2048 + 1024 + k4 * 4);
        reinterpret_cast<uint2*>(Wq2)[i] = conv4(v);
        return;
    }
    i -= N_WEP;
    if (i < N_ILV) {
        int r = i >> 8, k4 = i & 255;
        int sr = (r & 1) ? (r >> 1) + SDIM : (r >> 1);
        float4 v = *reinterpret_cast<const float4*>(Wpr_f + (size_t)sr * NDIM + k4 * 4);
        reinterpret_cast<uint2*>(Wpr)[i] = conv4(v);
        return;
    }
    i -= N_ILV;
    if (i < N_ILV) {
        int r = i >> 8, k4 = i & 255;
        int sr = (r & 1) ? (r >> 1) + SDIM : (r >> 1);
        float4 v = *reinterpret_cast<const float4*>(Wpo_f + (size_t)sr * NDIM + k4 * 4);
        reinterpret_cast<uint2*>(Wpo)[i] = conv4(v);
        return;
    }
    i -= N_ILV;
    if (i < N_H0) {
        split_store4(reinterpret_cast<const float4*>(prev_hidden)[i], hh, hl, i);
        return;
    }
    i -= N_H0;
    if (i < N_SP) {
        float4 v = reinterpret_cast<const float4*>(prev_state)[i];
        float s = nt0[i >> 5];
        v.x *= s; v.y *= s; v.z *= s; v.w *= s;
        split_store4(v, sph, spl, i);
        return;
    }
    i -= N_SP;
    if (i < N_ACT) {
        split_store4(reinterpret_cast<const float4*>(actions)[i], ah, al, i);
        return;
    }
    i -= N_ACT;
    if (i < N_CNT) {
        g_cnt[i] = 0u;
    }
}

// ------------------------------ GEMM args -----------------------------------
struct G {
    const half_t *Ah, *Al;
    const half_t *A2h, *A2l;
    const half_t* W;
    const float* bias;
    float* C; float* C2;
    const float* noise;      // EPI2: noise.  EPI4: hprev
    float* S;                // EPI2: state.  EPI4: hnew
    half_t *Ch, *Cl;         // EPI1/3 outs.  EPI4: gi/gh fp32 ptrs (uniform)
    half_t *Sh, *Sl;         // EPI2: sp out. EPI3: qe out. EPI4: h hi/lo out
    const float* ntNext;
    unsigned int* cnt;       // EPI4: grid-barrier counter (this step)
    int K, kSplit, sA, sA2;
};

// -------- fp16 2-pass tensor-core GEMM, cp.async 3-stage (C = A @ W^T) ------
// EPI: 0 bias->fp32; 1 bias+relu->fp16 hi/lo; 2 interleaved heads;
//      3 merged pe|qe; 4 = EPI0 store + grid barrier + fused GRU gate
template<int BM, int BN, int WM, int WN, int NWARPS, int EPI, int MINB>
__global__ __launch_bounds__(NWARPS * 32, MINB)
void gemm_tc(G g0, G g1, int N)
{
    constexpr int THREADS = NWARPS * 32;
    constexpr int BK  = 32;
    constexpr int LDS = BK + 8;
    constexpr int WTM = BM / WM;
    constexpr int WTN = BN / WN;
    constexpr int FM  = WTM / 16;
    constexpr int FN  = WTN / 8;
    static_assert(FN % 2 == 0, "");
    static_assert(WM * WN == NWARPS, "");
    constexpr int ACH = BM * 4;
    constexpr int BCH = BN * 4;
    constexpr int CH_TOT = 2 * ACH + BCH;
    constexpr int ABLK_B = BM * LDS * 2;
    constexpr int BBLK_B = BN * LDS * 2;
    constexpr int STG_B  = 2 * ABLK_B + BBLK_B;

    extern __shared__ __align__(16) char dynsmem[];
    const uint32_t sbase = (uint32_t)__cvta_generic_to_shared(dynsmem);

    const G g = (blockIdx.z == 0) ? g0 : g1;
    const int K = g.K;
    const int tid  = threadIdx.x;
    const int wid  = tid >> 5;
    const int lane = tid & 31;
    const int wm = wid % WM, wn = wid / WM;
    const int bm = blockIdx.y * BM, bn = blockIdx.x * BN;

    float acc[FM][FN][4];
#pragma unroll
    for (int i = 0; i < FM; i++)
#pragma unroll
        for (int j = 0; j < FN; j++)
#pragma unroll
            for (int q = 0; q < 4; q++) acc[i][j][q] = 0.0f;

    auto loadStage = [&](int ck, int buf) {
        const int ko = ck * BK;
        const half_t *ah, *al; int kb, sa;
        if (ko < g.kSplit) { ah = g.Ah;  al = g.Al;  kb = ko;             sa = g.sA;  }
        else               { ah = g.A2h; al = g.A2l; kb = ko - g.kSplit;  sa = g.sA2; }
        const uint32_t sb = sbase + (uint32_t)buf * STG_B;
#pragma unroll 2
        for (int i = tid; i < CH_TOT; i += THREADS) {
            const half_t* src; uint32_t dst;
            if (i < ACH) {
                int r = i >> 2, c = i & 3;
                src = ah + (size_t)(bm + r) * sa + kb + c * 8;
                dst = sb + (uint32_t)(r * LDS + c * 8) * 2;
            } else if (i < 2 * ACH) {
                int j = i - ACH;
                int r = j >> 2, c = j & 3;
                src = al + (size_t)(bm + r) * sa + kb + c * 8;
                dst = sb + ABLK_B + (uint32_t)(r * LDS + c * 8) * 2;
            } else {
                int j = i - 2 * ACH;
                int r = j >> 2, c = j & 3;
                src = g.W + (size_t)(bn + r) * K + ko + c * 8;
                dst = sb + 2 * ABLK_B + (uint32_t)(r * LDS + c * 8) * 2;
            }
            cp16(dst, src);
        }
    };

    const int kT = K / BK;
    loadStage(0, 0); cp_commit();
    loadStage(1, 1); cp_commit();

    int cbuf = 0, lbuf = 2;
    for (int kt = 0; kt < kT; kt++) {
        cp_wait1();
        __syncthreads();
        if (kt + 2 < kT) loadStage(kt + 2, lbuf);
        cp_commit();

        const uint32_t aBaseH = sbase + (uint32_t)cbuf * STG_B;
        const uint32_t aBaseL = aBaseH + ABLK_B;
        const uint32_t bBase  = aBaseH + 2 * ABLK_B;

#pragma unroll
        for (int k16 = 0; k16 < 2; k16++) {
            uint32_t afh[FM][4], afl[FM][4];
            const int acol = k16 * 16 + ((lane >> 4) << 3);
#pragma unroll
            for (int fm = 0; fm < FM; fm++) {
                const int arow = wm * WTM + fm * 16 + (lane & 15);
                const uint32_t aoff = (uint32_t)(arow * LDS + acol) * 2u;
                ldsm4(afh[fm], aBaseH + aoff);
                ldsm4(afl[fm], aBaseL + aoff);
            }
            const int brlane = ((lane >> 4) << 3) + (lane & 7);
            const int bcol   = k16 * 16 + (((lane >> 3) & 1) << 3);
#pragma unroll
            for (int fn2 = 0; fn2 < FN / 2; fn2++) {
                const int brow = wn * WTN + fn2 * 16 + brlane;
                const uint32_t boff = (uint32_t)(brow * LDS + bcol) * 2u;
                uint32_t bh[4];
                ldsm4(bh, bBase + boff);
#pragma unroll
                for (int fm = 0; fm < FM; fm++) {
                    float* c0 = acc[fm][2 * fn2];
                    float* c1 = acc[fm][2 * fn2 + 1];
                    mma_f16(c0, afh[fm], bh[0], bh[1]);
                    mma_f16(c0, afl[fm], bh[0], bh[1]);
                    mma_f16(c1, afh[fm], bh[2], bh[3]);
                    mma_f16(c1, afl[fm], bh[2], bh[3]);
                }
            }
        }
        __syncthreads();
        cbuf = (cbuf == 2) ? 0 : cbuf + 1;
        lbuf = (lbuf == 2) ? 0 : lbuf + 1;
    }

    const int gid = lane >> 2, tig = lane & 3;
#pragma unroll
    for (int fm = 0; fm < FM; fm++) {
        const int m0 = bm + wm * WTM + fm * 16 + gid;
#pragma unroll
        for (int fn = 0; fn < FN; fn++) {
            const int n0 = bn + wn * WTN + fn * 8 + tig * 2;
            if (EPI == 2) {
                const int i = n0 >> 1;
                const float bm_ = g.bias[i], bs_ = g.bias[i + SDIM];
                float me0 = acc[fm][fn][0] + bm_;
                float sd0 = softplusf_(acc[fm][fn][1] + bs_) + 0.1f;
                float me1 = acc[fm][fn][2] + bm_;
                float sd1 = softplusf_(acc[fm][fn][3] + bs_) + 0.1f;
                const size_t o0 = (size_t)m0 * SDIM + i;
                const size_t o1 = (size_t)(m0 + 8) * SDIM + i;
                g.C [o0] = me0;  g.C [o1] = me1;
                g.C2[o0] = sd0;  g.C2[o1] = sd1;
                float s0 = fmaf(sd0, g.noise[o0], me0);
                float s1 = fmaf(sd1, g.noise[o1], me1);
                g.S[o0] = s0;  g.S[o1] = s1;
                if (g.Sh) {
                    float sc0 = s0 * g.ntNext[m0];
                    float sc1 = s1 * g.ntNext[m0 + 8];
                    half_t h, l;
                    split_h(sc0, h, l); g.Sh[o0] = h; g.Sl[o0] = l;
                    split_h(sc1, h, l); g.Sh[o1] = h; g.Sl[o1] = l;
                }
            } else if (EPI == 3) {
                if (n0 < NDIM) {
                    const float b0 = g.bias[n0], b1 = g.bias[n0 + 1];
                    float v00 = fmaxf(acc[fm][fn][0] + b0, 0.0f);
                    float v01 = fmaxf(acc[fm][fn][1] + b1, 0.0f);
                    float v10 = fmaxf(acc[fm][fn][2] + b0, 0.0f);
                    float v11 = fmaxf(acc[fm][fn][3] + b1, 0.0f);
                    half_t h0, l0, h1, l1;
                    split_h(v00, h0, l0); split_h(v01, h1, l1);
                    *reinterpret_cast<uint32_t*>(g.Ch + (size_t)m0 * NDIM + n0) = pack_h2(h0, h1);
                    *reinterpret_cast<uint32_t*>(g.Cl + (size_t)m0 * NDIM + n0) = pack_h2(l0, l1);
                    split_h(v10, h0, l0); split_h(v11, h1, l1);
                    *reinterpret_cast<uint32_t*>(g.Ch + (size_t)(m0 + 8) * NDIM + n0) = pack_h2(h0, h1);
                    *reinterpret_cast<uint32_t*>(g.Cl + (size_t)(m0 + 8) * NDIM + n0) = pack_h2(l0, l1);
                } else {
                    const int nq = n0 - NDIM;
                    float2 p0 = *reinterpret_cast<const float2*>(g.C + (size_t)m0 * NDIM + nq);
                    float2 p1 = *reinterpret_cast<const float2*>(g.C + (size_t)(m0 + 8) * NDIM + nq);
                    float v00 = fmaxf(acc[fm][fn][0] + p0.x, 0.0f);
                    float v01 = fmaxf(acc[fm][fn][1] + p0.y, 0.0f);
                    float v10 = fmaxf(acc[fm][fn][2] + p1.x, 0.0f);
                    float v11 = fmaxf(acc[fm][fn][3] + p1.y, 0.0f);
                    half_t h0, l0, h1, l1;
                    split_h(v00, h0, l0); split_h(v01, h1, l1);
                    *reinterpret_cast<uint32_t*>(g.Sh + (size_t)m0 * NDIM + nq) = pack_h2(h0, h1);
                    *reinterpret_cast<uint32_t*>(g.Sl + (size_t)m0 * NDIM + nq) = pack_h2(l0, l1);
                    split_h(v10, h0, l0); split_h(v11, h1, l1);
                    *reinterpret_cast<uint32_t*>(g.Sh + (size_t)(m0 + 8) * NDIM + nq) = pack_h2(h0, h1);
                    *reinterpret_cast<uint32_t*>(g.Sl + (size_t)(m0 + 8) * NDIM + nq) = pack_h2(l0, l1);
                }
            } else {
                const float b0 = g.bias[n0], b1 = g.bias[n0 + 1];
                float v00 = acc[fm][fn][0] + b0, v01 = acc[fm][fn][1] + b1;
                float v10 = acc[fm][fn][2] + b0, v11 = acc[fm][fn][3] + b1;
                if (EPI == 1) {
                    v00 = fmaxf(v00, 0.0f); v01 = fmaxf(v01, 0.0f);
                    v10 = fmaxf(v10, 0.0f); v11 = fmaxf(v11, 0.0f);
                    half_t h0, l0, h1, l1;
                    split_h(v00, h0, l0); split_h(v01, h1, l1);
                    *reinterpret_cast<uint32_t*>(g.Ch + (size_t)m0 * N + n0) = pack_h2(h0, h1);
                    *reinterpret_cast<uint32_t*>(g.Cl + (size_t)m0 * N + n0) = pack_h2(l0, l1);
                    split_h(v10, h0, l0); split_h(v11, h1, l1);
                    *reinterpret_cast<uint32_t*>(g.Ch + (size_t)(m0 + 8) * N + n0) = pack_h2(h0, h1);
                    *reinterpret_cast<uint32_t*>(g.Cl + (size_t)(m0 + 8) * N + n0) = pack_h2(l0, l1);
                } else {   // EPI 0 and EPI 4: plain bias -> fp32
                    *reinterpret_cast<float2*>(g.C + (size_t)m0 * N + n0)       = make_float2(v00, v01);
                    *reinterpret_cast<float2*>(g.C + (size_t)(m0 + 8) * N + n0) = make_float2(v10, v11);
                }
            }
        }
    }

    if (EPI == 4) {
        // ---- grid barrier: all CTAs are co-resident (256 <= 148*2) ----
        const unsigned int TOTAL = gridDim.x * gridDim.y * gridDim.z;
        __threadfence();
        __syncthreads();
        if (tid == 0) {
            atomicAdd(g.cnt, 1u);
            volatile unsigned int* vc = (volatile unsigned int*)g.cnt;
            while (*vc < TOTAL) { __nanosleep(64); }
        }
        __syncthreads();
        __threadfence();

        // ---- fused GRU gate on this CTA's 1/TOTAL slice ----
        // gi/gh carried UNIFORMLY (same for both z-slices) via Ch/Cl.
        const float* giP = (const float*)g.Ch;
        const float* ghP = (const float*)g.Cl;
        const int flat = (blockIdx.z * gridDim.y + blockIdx.y) * gridDim.x + blockIdx.x;
        const int per  = (int)(BH / 4) / (int)TOTAL;        // float4 elems per CTA
        const int H4   = HDIM / 4;
        const float* hprev = g.noise;
        float* hnew = g.S;
        for (int it = 0; it < per; it += THREADS) {
            int idx4 = flat * per + it + tid;
            int m = idx4 / H4, j4 = idx4 % H4;
            const float4* gi4 = reinterpret_cast<const float4*>(giP + (size_t)m * 3 * HDIM);
            const float4* gh4 = reinterpret_cast<const float4*>(ghP + (size_t)m * 3 * HDIM);
            float4 ir = gi4[j4], iz = gi4[j4 + H4], in_ = gi4[j4 + 2 * H4];
            float4 hr = gh4[j4], hz = gh4[j4 + H4], hn = gh4[j4 + 2 * H4];
            float4 hp = reinterpret_cast<const float4*>(hprev + (size_t)m * HDIM)[j4];
            float4 o;
            { float r = sigmoidf_(ir.x + hr.x), z = sigmoidf_(iz.x + hz.x);
              float n = tanhf_(in_.x + r * hn.x); o.x = (1.0f - z) * n + z * hp.x; }
            { float r = sigmoidf_(ir.y + hr.y), z = sigmoidf_(iz.y + hz.y);
              float n = tanhf_(in_.y + r * hn.y); o.y = (1.0f - z) * n + z * hp.y; }
            { float r = sigmoidf_(ir.z + hr.z), z = sigmoidf_(iz.z + hz.z);
              float n = tanhf_(in_.z + r * hn.z); o.z = (1.0f - z) * n + z * hp.z; }
            { float r = sigmoidf_(ir.w + hr.w), z = sigmoidf_(iz.w + hz.w);
              float n = tanhf_(in_.w + r * hn.w); o.w = (1.0f - z) * n + z * hp.w; }
            reinterpret_cast<float4*>(hnew)[idx4] = o;
            split_store4(o, g.Sh, g.Sl, idx4);
        }
    }
}

// ------------------------------- launch --------------------------------------
extern "C" void kernel_launch(void* const* d_in, const int* in_sizes, int n_in,
                              void* d_out, int out_size)
{
    (void)in_sizes; (void)n_in; (void)out_size;
    const float* prev_hidden = (const float*)d_in[0];
    const float* prev_state  = (const float*)d_in[1];
    const float* actions     = (const float*)d_in[2];
    const float* obs         = (const float*)d_in[3];
    const float* non_terms   = (const float*)d_in[4];
    const float* prior_noise = (const float*)d_in[5];
    const float* post_noise  = (const float*)d_in[6];
    const float* W_sa = (const float*)d_in[7];
    const float* b_sa = (const float*)d_in[8];
    const float* W_ih = (const float*)d_in[9];
    const float* W_hh = (const float*)d_in[10];
    const float* b_ih = (const float*)d_in[11];
    const float* b_hh = (const float*)d_in[12];
    const float* W_ep = (const float*)d_in[13];
    const float* b_ep = (const float*)d_in[14];
    const float* W_pr = (const float*)d_in[15];
    const float* b_pr = (const float*)d_in[16];
    const float* W_eq = (const float*)d_in[17];
    const float* b_eq = (const float*)d_in[18];
    const float* W_po = (const float*)d_in[19];
    const float* b_po = (const float*)d_in[20];

    float* out = (float*)d_out;
    const size_t off_pm     = LBH;
    const size_t off_ps     = LBH + 1 * LBS;
    const size_t off_sprior = LBH + 2 * LBS;
    const size_t off_qm     = LBH + 3 * LBS;
    const size_t off_qs     = LBH + 4 * LBS;
    const size_t off_spost  = LBH + 5 * LBS;

    float *gi, *gh, *qp;
    cudaGetSymbolAddress((void**)&gi, g_gi);
    cudaGetSymbolAddress((void**)&gh, g_gh);
    cudaGetSymbolAddress((void**)&qp, g_qp);
    unsigned int* cnt;
    cudaGetSymbolAddress((void**)&cnt, g_cnt);
    half_t *x_h, *x_l, *h_h, *h_l, *pe_h, *pe_l, *qe_h, *qe_l, *ob_h, *ob_l;
    half_t *sp_h, *sp_l, *act_h, *act_l;
    cudaGetSymbolAddress((void**)&x_h,  g_x_h);  cudaGetSymbolAddress((void**)&x_l,  g_x_l);
    cudaGetSymbolAddress((void**)&h_h,  g_h_h);  cudaGetSymbolAddress((void**)&h_l,  g_h_l);
    cudaGetSymbolAddress((void**)&pe_h, g_pe_h); cudaGetSymbolAddress((void**)&pe_l, g_pe_l);
    cudaGetSymbolAddress((void**)&qe_h, g_qe_h); cudaGetSymbolAddress((void**)&qe_l, g_qe_l);
    cudaGetSymbolAddress((void**)&ob_h, g_ob_h); cudaGetSymbolAddress((void**)&ob_l, g_ob_l);
    cudaGetSymbolAddress((void**)&sp_h, g_sp_h); cudaGetSymbolAddress((void**)&sp_l, g_sp_l);
    cudaGetSymbolAddress((void**)&act_h, g_act_h); cudaGetSymbolAddress((void**)&act_l, g_act_l);

    half_t *Wsa, *Wih, *Whh, *Wpq, *Wq2, *Wpr, *Wpo;
    cudaGetSymbolAddress((void**)&Wsa, g_Wsa);
    cudaGetSymbolAddress((void**)&Wih, g_Wih);
    cudaGetSymbolAddress((void**)&Whh, g_Whh);
    cudaGetSymbolAddress((void**)&Wpq, g_Wpq);
    cudaGetSymbolAddress((void**)&Wq2, g_Wq2);
    cudaGetSymbolAddress((void**)&Wpr, g_Wpr);
    cudaGetSymbolAddress((void**)&Wpo, g_Wpo);

    // ---- dynamic smem ----
    const int SM_BIG  = 3 * (2 * 128 * 40 + 96 * 40) * 2;    // 84480 (2 CTAs/SM)
    const int SM_PQB  = 3 * (2 * 64 * 40 + 128 * 40) * 2;    // 61440
    const int SM_X    = 3 * (2 * 64 * 40 + 64 * 40) * 2;     // 46080
    const int SM_HEAD = 3 * (2 * 32 * 40 + 64 * 40) * 2;     // 30720
    cudaFuncSetAttribute((const void*)gemm_tc<128, 96, 4, 2, 8, 4, 2>,
                         cudaFuncAttributeMaxDynamicSharedMemorySize, SM_BIG);
    cudaFuncSetAttribute((const void*)gemm_tc<64, 128, 2, 4, 8, 0, 1>,
                         cudaFuncAttributeMaxDynamicSharedMemorySize, SM_PQB);
    cudaFuncSetAttribute((const void*)gemm_tc<64, 64, 2, 4, 8, 3, 2>,
                         cudaFuncAttributeMaxDynamicSharedMemorySize, SM_X);
    cudaFuncSetAttribute((const void*)gemm_tc<64, 64, 2, 4, 8, 1, 1>,
                         cudaFuncAttributeMaxDynamicSharedMemorySize, SM_X);
    cudaFuncSetAttribute((const void*)gemm_tc<32, 64, 1, 4, 4, 2, 1>,
                         cudaFuncAttributeMaxDynamicSharedMemorySize, SM_HEAD);

    // ---- launch 0: one-shot prep (also zeroes barrier counters) ----
    prep_kernel<<<(N_TOT + 255) / 256, 256>>>(
        W_ih, W_hh, W_sa, W_ep, W_eq, W_pr, W_po,
        prev_hidden, prev_state, non_terms, actions, obs,
        Wih, Whh, Wsa, Wpq, Wq2, Wpr, Wpo,
        h_h, h_l, sp_h, sp_l, act_h, act_l, ob_h, ob_l);

    // ---- launch 1: batched qe obs-partial ----
    {
        G a{ob_h, ob_l, ob_h, ob_l, Wq2, b_eq, qp, nullptr, nullptr, nullptr,
            nullptr, nullptr, nullptr, nullptr, nullptr, nullptr, EDIM, EDIM, EDIM, EDIM};
        gemm_tc<64, 128, 2, 4, 8, 0, 1><<<dim3(NDIM / 128, LSTEPS * BDIM / 64, 1), 256, SM_PQB>>>(
            a, a, NDIM);
    }

    const int KSA = SDIM + ADIM;

    for (int t = 0; t < LSTEPS; t++) {
        const float* hprev = (t == 0) ? prev_hidden : out + (size_t)(t - 1) * BH;
        float* hnew = out + (size_t)t * BH;
        const half_t* act_ht = act_h + (size_t)t * BDIM * ADIM;
        const half_t* act_lt = act_l + (size_t)t * BDIM * ADIM;
        const float* ntNext = non_terms + (size_t)((t + 1 < LSTEPS) ? t + 1 : t) * BDIM;
        float* qp_t = qp + (size_t)t * BDIM * NDIM;

        // x = relu([spost*nt, a] @ Wsa^T + b_sa)
        {
            G a{sp_h, sp_l, act_ht, act_lt, Wsa, b_sa,
                nullptr, nullptr, nullptr, nullptr, x_h, x_l,
                nullptr, nullptr, nullptr, nullptr, KSA, SDIM, SDIM, ADIM};
            gemm_tc<64, 64, 2, 4, 8, 1, 1><<<dim3(HDIM / 64, BDIM / 64, 1), 256, SM_X>>>(
                a, a, HDIM);
        }
        // gi/gh big GEMM + grid barrier + fused GRU gate (idx 3 at t=0 -> profiled)
        {
            G a0{x_h, x_l, x_h, x_l, Wih, b_ih, gi, nullptr, hprev, hnew,
                 (half_t*)gi, (half_t*)gh, h_h, h_l, nullptr, cnt + t,
                 HDIM, HDIM, HDIM, HDIM};
            G a1{h_h, h_l, h_h, h_l, Whh, b_hh, gh, nullptr, hprev, hnew,
                 (half_t*)gi, (half_t*)gh, h_h, h_l, nullptr, cnt + t,
                 HDIM, HDIM, HDIM, HDIM};
            gemm_tc<128, 96, 4, 2, 8, 4, 2><<<dim3(3 * HDIM / 96, BDIM / 128, 2), 256, SM_BIG>>>(
                a0, a1, 3 * HDIM);
        }
        // merged pe|qe
        {
            G a{h_h, h_l, h_h, h_l, Wpq, b_ep, qp_t, nullptr, nullptr, nullptr,
                pe_h, pe_l, qe_h, qe_l, nullptr, nullptr, HDIM, HDIM, HDIM, HDIM};
            gemm_tc<64, 64, 2, 4, 8, 3, 2><<<dim3(2 * NDIM / 64, BDIM / 64, 1), 256, SM_X>>>(
                a, a, 2 * NDIM);
        }
        // heads + reparameterized states
        float* pm_o = out + off_pm + (size_t)t * BS;
        float* ps_o = out + off_ps + (size_t)t * BS;
        float* qm_o = out + off_qm + (size_t)t * BS;
        float* qs_o = out + off_qs + (size_t)t * BS;
        {
            G a0{pe_h, pe_l, pe_h, pe_l, Wpr, b_pr, pm_o, ps_o,
                 prior_noise + (size_t)t * BS, out + off_sprior + (size_t)t * BS,
                 nullptr, nullptr, nullptr, nullptr, nullptr, nullptr, NDIM, NDIM, NDIM, NDIM};
            G a1{qe_h, qe_l, qe_h, qe_l, Wpo, b_po, qm_o, qs_o,
                 post_noise + (size_t)t * BS, out + off_spost + (size_t)t * BS,
                 nullptr, nullptr, sp_h, sp_l, ntNext, nullptr, NDIM, NDIM, NDIM, NDIM};
            gemm_tc<32, 64, 1, 4, 4, 2, 1><<<dim3(2 * SDIM / 64, BDIM / 32, 2), 128, SM_HEAD>>>(
                a0, a1, 2 * SDIM);
        }
    }
}

// round 16
// speedup vs baseline: 1.5567x; 1.5567x over previous
#include <cuda_runtime.h>
#include <cuda_fp16.h>
#include <math.h>
#include <stdint.h>

#define LSTEPS 64
#define BDIM   512
#define HDIM   1024
#define SDIM   128
#define ADIM   32
#define NDIM   1024
#define EDIM   1024

#define BH ((size_t)BDIM * HDIM)
#define BS ((size_t)BDIM * SDIM)
#define LBH ((size_t)LSTEPS * BH)
#define LBS ((size_t)LSTEPS * BS)
#define LACT (LSTEPS * BDIM * ADIM)
#define LOBS ((size_t)LSTEPS * BDIM * EDIM)

typedef __half half_t;

// ---------------- scratch: fp32 ---------------------------------------------
__device__ __align__(16) float g_gi[BDIM * 3 * HDIM];
__device__ __align__(16) float g_gh[BDIM * 3 * HDIM];
__device__ __align__(16) float g_qp[LOBS];            // qe obs-partial (+b_eq)

// ---------------- scratch: fp16 activations (single precision pass) ---------
__device__ __align__(16) half_t g_x [BDIM * HDIM];
__device__ __align__(16) half_t g_h [BDIM * HDIM];
__device__ __align__(16) half_t g_pe[BDIM * NDIM];
__device__ __align__(16) half_t g_qe[BDIM * NDIM];
__device__ __align__(16) half_t g_sp[BDIM * SDIM];
__device__ __align__(16) half_t g_act[LACT];
__device__ __align__(16) half_t g_ob[LOBS];

// ---------------- scratch: converted weights (fp16) -------------------------
#define SZ_WSA (HDIM * (SDIM + ADIM))
#define SZ_WIH (3 * HDIM * HDIM)
#define SZ_WEP (NDIM * HDIM)
#define SZ_WPR (2 * SDIM * NDIM)

__device__ __align__(16) half_t g_Wsa[SZ_WSA];
__device__ __align__(16) half_t g_Wih[SZ_WIH];
__device__ __align__(16) half_t g_Whh[SZ_WIH];
__device__ __align__(16) half_t g_Wpq[2 * NDIM * HDIM];   // [Wep; Weq[:, :1024]]
__device__ __align__(16) half_t g_Wq2[NDIM * EDIM];       // Weq[:, 1024:]
__device__ __align__(16) half_t g_Wpr[SZ_WPR];            // row-interleaved mean/std
__device__ __align__(16) half_t g_Wpo[SZ_WPR];

// ------------------------------- helpers ------------------------------------
__device__ __forceinline__ float sigmoidf_(float x) { return 1.0f / (1.0f + __expf(-x)); }
__device__ __forceinline__ float tanhf_(float x)    { return 1.0f - 2.0f / (__expf(2.0f * x) + 1.0f); }
__device__ __forceinline__ float softplusf_(float x) {
    return fmaxf(x, 0.0f) + log1pf(__expf(-fabsf(x)));
}
__device__ __forceinline__ uint32_t pack_h2(half_t a, half_t b) {
    __half2 t(a, b);
    return *reinterpret_cast<uint32_t*>(&t);
}
__device__ __forceinline__ uint2 conv4(float4 v) {
    return make_uint2(pack_h2(__float2half_rn(v.x), __float2half_rn(v.y)),
                      pack_h2(__float2half_rn(v.z), __float2half_rn(v.w)));
}
__device__ __forceinline__ void ldsm4(uint32_t* r, uint32_t addr) {
    asm volatile("ldmatrix.sync.aligned.m8n8.x4.shared.b16 {%0,%1,%2,%3}, [%4];"
                 : "=r"(r[0]), "=r"(r[1]), "=r"(r[2]), "=r"(r[3]) : "r"(addr));
}
__device__ __forceinline__ void mma_f16(float* c, const uint32_t* a, uint32_t b0, uint32_t b1) {
    asm volatile("mma.sync.aligned.m16n8k16.row.col.f32.f16.f16.f32 "
                 "{%0,%1,%2,%3}, {%4,%5,%6,%7}, {%8,%9}, {%0,%1,%2,%3};"
                 : "+f"(c[0]), "+f"(c[1]), "+f"(c[2]), "+f"(c[3])
                 : "r"(a[0]), "r"(a[1]), "r"(a[2]), "r"(a[3]), "r"(b0), "r"(b1));
}
__device__ __forceinline__ void cp16(uint32_t dst, const void* src) {
    asm volatile("cp.async.cg.shared.global [%0], [%1], 16;" :: "r"(dst), "l"(src));
}
__device__ __forceinline__ void cp_commit() {
    asm volatile("cp.async.commit_group;" ::: "memory");
}
__device__ __forceinline__ void cp_wait1() {
    asm volatile("cp.async.wait_group 1;" ::: "memory");
}

// -------------------- one-shot prep (all converts, flat dispatch) -----------
#define N_OBS  ((int)(LOBS / 4))
#define N_WIH  (SZ_WIH / 4)
#define N_WSA  (SZ_WSA / 4)
#define N_WEP  (SZ_WEP / 4)
#define N_ILV  (SZ_WPR / 4)
#define N_H0   ((int)(BH / 4))
#define N_SP   ((int)(BS / 4))
#define N_ACT  (LACT / 4)
#define N_TOT  (N_OBS + 2 * N_WIH + N_WSA + 3 * N_WEP + 2 * N_ILV + N_H0 + N_SP + N_ACT)

__global__ void prep_kernel(
    const float* __restrict__ Wih_f, const float* __restrict__ Whh_f,
    const float* __restrict__ Wsa_f, const float* __restrict__ Wep_f,
    const float* __restrict__ Weq_f, const float* __restrict__ Wpr_f,
    const float* __restrict__ Wpo_f,
    const float* __restrict__ prev_hidden, const float* __restrict__ prev_state,
    const float* __restrict__ nt0, const float* __restrict__ actions,
    const float* __restrict__ obs,
    half_t* __restrict__ Wih, half_t* __restrict__ Whh, half_t* __restrict__ Wsa,
    half_t* __restrict__ Wpq, half_t* __restrict__ Wq2,
    half_t* __restrict__ Wpr, half_t* __restrict__ Wpo,
    half_t* __restrict__ hh, half_t* __restrict__ sph,
    half_t* __restrict__ ah, half_t* __restrict__ oh)
{
    int i = blockIdx.x * blockDim.x + threadIdx.x;
    if (i < N_OBS) {
        reinterpret_cast<uint2*>(oh)[i] = conv4(reinterpret_cast<const float4*>(obs)[i]);
        return;
    }
    i -= N_OBS;
    if (i < N_WIH) {
        reinterpret_cast<uint2*>(Wih)[i] = conv4(reinterpret_cast<const float4*>(Wih_f)[i]);
        return;
    }
    i -= N_WIH;
    if (i < N_WIH) {
        reinterpret_cast<uint2*>(Whh)[i] = conv4(reinterpret_cast<const float4*>(Whh_f)[i]);
        return;
    }
    i -= N_WIH;
    if (i < N_WSA) {
        reinterpret_cast<uint2*>(Wsa)[i] = conv4(reinterpret_cast<const float4*>(Wsa_f)[i]);
        return;
    }
    i -= N_WSA;
    if (i < N_WEP) {
        reinterpret_cast<uint2*>(Wpq)[i] = conv4(reinterpret_cast<const float4*>(Wep_f)[i]);
        return;
    }
    i -= N_WEP;
    if (i < N_WEP) {
        int n = i >> 8, k4 = i & 255;
        float4 v = *reinterpret_cast<const float4*>(Weq_f + (size_t)n * 2048 + k4 * 4);
        reinterpret_cast<uint2*>(Wpq)[N_WEP + i] = conv4(v);
        return;
    }
    i -= N_WEP;
    if (i < N_WEP) {
        int n = i >> 8, k4 = i & 255;
        float4 v = *reinterpret_cast<const float4*>(Weq_f + (size_t)n * 2048 + 1024 + k4 * 4);
        reinterpret_cast<uint2*>(Wq2)[i] = conv4(v);
        return;
    }
    i -= N_WEP;
    if (i < N_ILV) {
        int r = i >> 8, k4 = i & 255;
        int sr = (r & 1) ? (r >> 1) + SDIM : (r >> 1);
        float4 v = *reinterpret_cast<const float4*>(Wpr_f + (size_t)sr * NDIM + k4 * 4);
        reinterpret_cast<uint2*>(Wpr)[i] = conv4(v);
        return;
    }
    i -= N_ILV;
    if (i < N_ILV) {
        int r = i >> 8, k4 = i & 255;
        int sr = (r & 1) ? (r >> 1) + SDIM : (r >> 1);
        float4 v = *reinterpret_cast<const float4*>(Wpo_f + (size_t)sr * NDIM + k4 * 4);
        reinterpret_cast<uint2*>(Wpo)[i] = conv4(v);
        return;
    }
    i -= N_ILV;
    if (i < N_H0) {
        reinterpret_cast<uint2*>(hh)[i] = conv4(reinterpret_cast<const float4*>(prev_hidden)[i]);
        return;
    }
    i -= N_H0;
    if (i < N_SP) {
        float4 v = reinterpret_cast<const float4*>(prev_state)[i];
        float s = nt0[i >> 5];
        v.x *= s; v.y *= s; v.z *= s; v.w *= s;
        reinterpret_cast<uint2*>(sph)[i] = conv4(v);
        return;
    }
    i -= N_SP;
    if (i < N_ACT) {
        reinterpret_cast<uint2*>(ah)[i] = conv4(reinterpret_cast<const float4*>(actions)[i]);
    }
}

// ------------------------------ GEMM args -----------------------------------
struct G {
    const half_t* A;       // k < kSplit, row stride sA
    const half_t* A2;      // k >= kSplit, row stride sA2
    const half_t* W;       // N x K fp16 row-major
    const float* bias;
    float* C; float* C2;   // EPI0: C out. EPI2: mean/std. EPI3: qe partial in
    const float* noise;    // EPI2
    float* S;              // EPI2: state out
    half_t *Ch;            // EPI1: out. EPI3: pe out
    half_t *Sh;            // EPI2: spost*nt out. EPI3: qe out
    const float* ntNext;   // EPI2
    int K, kSplit, sA, sA2;
};

// -------- fp16 single-pass tensor-core GEMM, cp.async 3-stage ---------------
// EPI: 0 bias->fp32; 1 bias+relu->fp16; 2 interleaved heads;
//      3 merged pe|qe (n<1024: bias+relu->Ch; else: +partial, relu->Sh)
template<int BM, int BN, int WM, int WN, int NWARPS, int EPI, int MINB>
__global__ __launch_bounds__(NWARPS * 32, MINB)
void gemm_tc(G g0, G g1, int N)
{
    constexpr int THREADS = NWARPS * 32;
    constexpr int BK  = 32;
    constexpr int LDS = BK + 8;
    constexpr int WTM = BM / WM;
    constexpr int WTN = BN / WN;
    constexpr int FM  = WTM / 16;
    constexpr int FN  = WTN / 8;
    static_assert(FN % 2 == 0, "");
    static_assert(WM * WN == NWARPS, "");
    constexpr int ACH = BM * 4;
    constexpr int BCH = BN * 4;
    constexpr int CH_TOT = ACH + BCH;
    constexpr int ABLK_B = BM * LDS * 2;
    constexpr int BBLK_B = BN * LDS * 2;
    constexpr int STG_B  = ABLK_B + BBLK_B;

    extern __shared__ __align__(16) char dynsmem[];
    const uint32_t sbase = (uint32_t)__cvta_generic_to_shared(dynsmem);

    const G g = (blockIdx.z == 0) ? g0 : g1;
    const int K = g.K;
    const int tid  = threadIdx.x;
    const int wid  = tid >> 5;
    const int lane = tid & 31;
    const int wm = wid % WM, wn = wid / WM;
    const int bm = blockIdx.y * BM, bn = blockIdx.x * BN;

    float acc[FM][FN][4];
#pragma unroll
    for (int i = 0; i < FM; i++)
#pragma unroll
        for (int j = 0; j < FN; j++)
#pragma unroll
            for (int q = 0; q < 4; q++) acc[i][j][q] = 0.0f;

    auto loadStage = [&](int ck, int buf) {
        const int ko = ck * BK;
        const half_t* ah; int kb, sa;
        if (ko < g.kSplit) { ah = g.A;  kb = ko;             sa = g.sA;  }
        else               { ah = g.A2; kb = ko - g.kSplit;  sa = g.sA2; }
        const uint32_t sb = sbase + (uint32_t)buf * STG_B;
#pragma unroll 2
        for (int i = tid; i < CH_TOT; i += THREADS) {
            const half_t* src; uint32_t dst;
            if (i < ACH) {
                int r = i >> 2, c = i & 3;
                src = ah + (size_t)(bm + r) * sa + kb + c * 8;
                dst = sb + (uint32_t)(r * LDS + c * 8) * 2;
            } else {
                int j = i - ACH;
                int r = j >> 2, c = j & 3;
                src = g.W + (size_t)(bn + r) * K + ko + c * 8;
                dst = sb + ABLK_B + (uint32_t)(r * LDS + c * 8) * 2;
            }
            cp16(dst, src);
        }
    };

    const int kT = K / BK;
    loadStage(0, 0); cp_commit();
    loadStage(1, 1); cp_commit();

    int cbuf = 0, lbuf = 2;
    for (int kt = 0; kt < kT; kt++) {
        cp_wait1();
        __syncthreads();
        if (kt + 2 < kT) loadStage(kt + 2, lbuf);
        cp_commit();

        const uint32_t aBase = sbase + (uint32_t)cbuf * STG_B;
        const uint32_t bBase = aBase + ABLK_B;

#pragma unroll
        for (int k16 = 0; k16 < 2; k16++) {
            uint32_t af[FM][4];
            const int acol = k16 * 16 + ((lane >> 4) << 3);
#pragma unroll
            for (int fm = 0; fm < FM; fm++) {
                const int arow = wm * WTM + fm * 16 + (lane & 15);
                const uint32_t aoff = (uint32_t)(arow * LDS + acol) * 2u;
                ldsm4(af[fm], aBase + aoff);
            }
            const int brlane = ((lane >> 4) << 3) + (lane & 7);
            const int bcol   = k16 * 16 + (((lane >> 3) & 1) << 3);
#pragma unroll
            for (int fn2 = 0; fn2 < FN / 2; fn2++) {
                const int brow = wn * WTN + fn2 * 16 + brlane;
                const uint32_t boff = (uint32_t)(brow * LDS + bcol) * 2u;
                uint32_t bh[4];
                ldsm4(bh, bBase + boff);
#pragma unroll
                for (int fm = 0; fm < FM; fm++) {
                    mma_f16(acc[fm][2 * fn2],     af[fm], bh[0], bh[1]);
                    mma_f16(acc[fm][2 * fn2 + 1], af[fm], bh[2], bh[3]);
                }
            }
        }
        __syncthreads();
        cbuf = (cbuf == 2) ? 0 : cbuf + 1;
        lbuf = (lbuf == 2) ? 0 : lbuf + 1;
    }

    const int gid = lane >> 2, tig = lane & 3;
#pragma unroll
    for (int fm = 0; fm < FM; fm++) {
        const int m0 = bm + wm * WTM + fm * 16 + gid;
#pragma unroll
        for (int fn = 0; fn < FN; fn++) {
            const int n0 = bn + wn * WTN + fn * 8 + tig * 2;
            if (EPI == 2) {
                const int i = n0 >> 1;
                const float bm_ = g.bias[i], bs_ = g.bias[i + SDIM];
                float me0 = acc[fm][fn][0] + bm_;
                float sd0 = softplusf_(acc[fm][fn][1] + bs_) + 0.1f;
                float me1 = acc[fm][fn][2] + bm_;
                float sd1 = softplusf_(acc[fm][fn][3] + bs_) + 0.1f;
                const size_t o0 = (size_t)m0 * SDIM + i;
                const size_t o1 = (size_t)(m0 + 8) * SDIM + i;
                g.C [o0] = me0;  g.C [o1] = me1;
                g.C2[o0] = sd0;  g.C2[o1] = sd1;
                float s0 = fmaf(sd0, g.noise[o0], me0);
                float s1 = fmaf(sd1, g.noise[o1], me1);
                g.S[o0] = s0;  g.S[o1] = s1;
                if (g.Sh) {
                    g.Sh[o0] = __float2half_rn(s0 * g.ntNext[m0]);
                    g.Sh[o1] = __float2half_rn(s1 * g.ntNext[m0 + 8]);
                }
            } else if (EPI == 3) {
                if (n0 < NDIM) {
                    const float b0 = g.bias[n0], b1 = g.bias[n0 + 1];
                    float v00 = fmaxf(acc[fm][fn][0] + b0, 0.0f);
                    float v01 = fmaxf(acc[fm][fn][1] + b1, 0.0f);
                    float v10 = fmaxf(acc[fm][fn][2] + b0, 0.0f);
                    float v11 = fmaxf(acc[fm][fn][3] + b1, 0.0f);
                    *reinterpret_cast<uint32_t*>(g.Ch + (size_t)m0 * NDIM + n0) =
                        pack_h2(__float2half_rn(v00), __float2half_rn(v01));
                    *reinterpret_cast<uint32_t*>(g.Ch + (size_t)(m0 + 8) * NDIM + n0) =
                        pack_h2(__float2half_rn(v10), __float2half_rn(v11));
                } else {
                    const int nq = n0 - NDIM;
                    float2 p0 = *reinterpret_cast<const float2*>(g.C + (size_t)m0 * NDIM + nq);
                    float2 p1 = *reinterpret_cast<const float2*>(g.C + (size_t)(m0 + 8) * NDIM + nq);
                    float v00 = fmaxf(acc[fm][fn][0] + p0.x, 0.0f);
                    float v01 = fmaxf(acc[fm][fn][1] + p0.y, 0.0f);
                    float v10 = fmaxf(acc[fm][fn][2] + p1.x, 0.0f);
                    float v11 = fmaxf(acc[fm][fn][3] + p1.y, 0.0f);
                    *reinterpret_cast<uint32_t*>(g.Sh + (size_t)m0 * NDIM + nq) =
                        pack_h2(__float2half_rn(v00), __float2half_rn(v01));
                    *reinterpret_cast<uint32_t*>(g.Sh + (size_t)(m0 + 8) * NDIM + nq) =
                        pack_h2(__float2half_rn(v10), __float2half_rn(v11));
                }
            } else {
                const float b0 = g.bias[n0], b1 = g.bias[n0 + 1];
                float v00 = acc[fm][fn][0] + b0, v01 = acc[fm][fn][1] + b1;
                float v10 = acc[fm][fn][2] + b0, v11 = acc[fm][fn][3] + b1;
                if (EPI == 1) {
                    v00 = fmaxf(v00, 0.0f); v01 = fmaxf(v01, 0.0f);
                    v10 = fmaxf(v10, 0.0f); v11 = fmaxf(v11, 0.0f);
                    *reinterpret_cast<uint32_t*>(g.Ch + (size_t)m0 * N + n0) =
                        pack_h2(__float2half_rn(v00), __float2half_rn(v01));
                    *reinterpret_cast<uint32_t*>(g.Ch + (size_t)(m0 + 8) * N + n0) =
                        pack_h2(__float2half_rn(v10), __float2half_rn(v11));
                } else {
                    *reinterpret_cast<float2*>(g.C + (size_t)m0 * N + n0)       = make_float2(v00, v01);
                    *reinterpret_cast<float2*>(g.C + (size_t)(m0 + 8) * N + n0) = make_float2(v10, v11);
                }
            }
        }
    }
}

// ---------------- GRU gates + h fp16 ----------------------------------------
__global__ void gru_gate_kernel(const float* __restrict__ hprev, float* __restrict__ hnew,
                                half_t* __restrict__ hh)
{
    const int H4 = HDIM / 4;
    int idx = blockIdx.x * blockDim.x + threadIdx.x;
    if (idx >= BDIM * H4) return;
    int m = idx / H4, j4 = idx % H4;
    const float4* gi = reinterpret_cast<const float4*>(g_gi + (size_t)m * 3 * HDIM);
    const float4* gh = reinterpret_cast<const float4*>(g_gh + (size_t)m * 3 * HDIM);
    float4 ir = gi[j4], iz = gi[j4 + H4], in_ = gi[j4 + 2 * H4];
    float4 hr = gh[j4], hz = gh[j4 + H4], hn = gh[j4 + 2 * H4];
    float4 hp = reinterpret_cast<const float4*>(hprev + (size_t)m * HDIM)[j4];
    float4 o;
    { float r = sigmoidf_(ir.x + hr.x), z = sigmoidf_(iz.x + hz.x);
      float n = tanhf_(in_.x + r * hn.x); o.x = (1.0f - z) * n + z * hp.x; }
    { float r = sigmoidf_(ir.y + hr.y), z = sigmoidf_(iz.y + hz.y);
      float n = tanhf_(in_.y + r * hn.y); o.y = (1.0f - z) * n + z * hp.y; }
    { float r = sigmoidf_(ir.z + hr.z), z = sigmoidf_(iz.z + hz.z);
      float n = tanhf_(in_.z + r * hn.z); o.z = (1.0f - z) * n + z * hp.z; }
    { float r = sigmoidf_(ir.w + hr.w), z = sigmoidf_(iz.w + hz.w);
      float n = tanhf_(in_.w + r * hn.w); o.w = (1.0f - z) * n + z * hp.w; }
    reinterpret_cast<float4*>(hnew)[idx] = o;
    reinterpret_cast<uint2*>(hh)[idx] = conv4(o);
}

// ------------------------------- launch --------------------------------------
extern "C" void kernel_launch(void* const* d_in, const int* in_sizes, int n_in,
                              void* d_out, int out_size)
{
    (void)in_sizes; (void)n_in; (void)out_size;
    const float* prev_hidden = (const float*)d_in[0];
    const float* prev_state  = (const float*)d_in[1];
    const float* actions     = (const float*)d_in[2];
    const float* obs         = (const float*)d_in[3];
    const float* non_terms   = (const float*)d_in[4];
    const float* prior_noise = (const float*)d_in[5];
    const float* post_noise  = (const float*)d_in[6];
    const float* W_sa = (const float*)d_in[7];
    const float* b_sa = (const float*)d_in[8];
    const float* W_ih = (const float*)d_in[9];
    const float* W_hh = (const float*)d_in[10];
    const float* b_ih = (const float*)d_in[11];
    const float* b_hh = (const float*)d_in[12];
    const float* W_ep = (const float*)d_in[13];
    const float* b_ep = (const float*)d_in[14];
    const float* W_pr = (const float*)d_in[15];
    const float* b_pr = (const float*)d_in[16];
    const float* W_eq = (const float*)d_in[17];
    const float* b_eq = (const float*)d_in[18];
    const float* W_po = (const float*)d_in[19];
    const float* b_po = (const float*)d_in[20];

    float* out = (float*)d_out;
    const size_t off_pm     = LBH;
    const size_t off_ps     = LBH + 1 * LBS;
    const size_t off_sprior = LBH + 2 * LBS;
    const size_t off_qm     = LBH + 3 * LBS;
    const size_t off_qs     = LBH + 4 * LBS;
    const size_t off_spost  = LBH + 5 * LBS;

    float *gi, *gh, *qp;
    cudaGetSymbolAddress((void**)&gi, g_gi);
    cudaGetSymbolAddress((void**)&gh, g_gh);
    cudaGetSymbolAddress((void**)&qp, g_qp);
    half_t *x_, *h_, *pe_, *qe_, *ob_, *sp_, *act_;
    cudaGetSymbolAddress((void**)&x_,  g_x);
    cudaGetSymbolAddress((void**)&h_,  g_h);
    cudaGetSymbolAddress((void**)&pe_, g_pe);
    cudaGetSymbolAddress((void**)&qe_, g_qe);
    cudaGetSymbolAddress((void**)&ob_, g_ob);
    cudaGetSymbolAddress((void**)&sp_, g_sp);
    cudaGetSymbolAddress((void**)&act_, g_act);

    half_t *Wsa, *Wih, *Whh, *Wpq, *Wq2, *Wpr, *Wpo;
    cudaGetSymbolAddress((void**)&Wsa, g_Wsa);
    cudaGetSymbolAddress((void**)&Wih, g_Wih);
    cudaGetSymbolAddress((void**)&Whh, g_Whh);
    cudaGetSymbolAddress((void**)&Wpq, g_Wpq);
    cudaGetSymbolAddress((void**)&Wq2, g_Wq2);
    cudaGetSymbolAddress((void**)&Wpr, g_Wpr);
    cudaGetSymbolAddress((void**)&Wpo, g_Wpo);

    // ---- dynamic smem (single-pass: stage = (BM + BN) * 40 * 2 bytes) ----
    const int SM_BIG  = 3 * (128 + 96)  * 40 * 2;   // 53760 (2+ CTAs/SM)
    const int SM_PQB  = 3 * (64 + 128)  * 40 * 2;   // 46080
    const int SM_X    = 3 * (64 + 64)   * 40 * 2;   // 30720
    const int SM_HEAD = 3 * (32 + 64)   * 40 * 2;   // 23040
    cudaFuncSetAttribute((const void*)gemm_tc<128, 96, 4, 2, 8, 0, 2>,
                         cudaFuncAttributeMaxDynamicSharedMemorySize, SM_BIG);
    cudaFuncSetAttribute((const void*)gemm_tc<64, 128, 2, 4, 8, 0, 1>,
                         cudaFuncAttributeMaxDynamicSharedMemorySize, SM_PQB);
    cudaFuncSetAttribute((const void*)gemm_tc<64, 64, 2, 4, 8, 3, 2>,
                         cudaFuncAttributeMaxDynamicSharedMemorySize, SM_X);
    cudaFuncSetAttribute((const void*)gemm_tc<64, 64, 2, 4, 8, 1, 1>,
                         cudaFuncAttributeMaxDynamicSharedMemorySize, SM_X);
    cudaFuncSetAttribute((const void*)gemm_tc<32, 64, 1, 4, 4, 2, 1>,
                         cudaFuncAttributeMaxDynamicSharedMemorySize, SM_HEAD);

    // ---- launch 0: one-shot prep ----
    prep_kernel<<<(N_TOT + 255) / 256, 256>>>(
        W_ih, W_hh, W_sa, W_ep, W_eq, W_pr, W_po,
        prev_hidden, prev_state, non_terms, actions, obs,
        Wih, Whh, Wsa, Wpq, Wq2, Wpr, Wpo,
        h_, sp_, act_, ob_);

    // ---- launch 1: batched qe obs-partial ----
    {
        G a{ob_, ob_, Wq2, b_eq, qp, nullptr, nullptr, nullptr,
            nullptr, nullptr, nullptr, EDIM, EDIM, EDIM, EDIM};
        gemm_tc<64, 128, 2, 4, 8, 0, 1><<<dim3(NDIM / 128, LSTEPS * BDIM / 64, 1), 256, SM_PQB>>>(
            a, a, NDIM);
    }

    const int KSA = SDIM + ADIM;

    for (int t = 0; t < LSTEPS; t++) {
        const float* hprev = (t == 0) ? prev_hidden : out + (size_t)(t - 1) * BH;
        float* hnew = out + (size_t)t * BH;
        const half_t* act_t = act_ + (size_t)t * BDIM * ADIM;
        const float* ntNext = non_terms + (size_t)((t + 1 < LSTEPS) ? t + 1 : t) * BDIM;
        float* qp_t = qp + (size_t)t * BDIM * NDIM;

        // x = relu([spost*nt, a] @ Wsa^T + b_sa)
        {
            G a{sp_, act_t, Wsa, b_sa, nullptr, nullptr, nullptr, nullptr,
                x_, nullptr, nullptr, KSA, SDIM, SDIM, ADIM};
            gemm_tc<64, 64, 2, 4, 8, 1, 1><<<dim3(HDIM / 64, BDIM / 64, 1), 256, SM_X>>>(
                a, a, HDIM);
        }
        // gi/gh big GEMM: 256 CTAs, 2 CTAs/SM  (idx 3 at t=0 -> profiled)
        {
            G a0{x_, x_, Wih, b_ih, gi, nullptr, nullptr, nullptr,
                 nullptr, nullptr, nullptr, HDIM, HDIM, HDIM, HDIM};
            G a1{h_, h_, Whh, b_hh, gh, nullptr, nullptr, nullptr,
                 nullptr, nullptr, nullptr, HDIM, HDIM, HDIM, HDIM};
            gemm_tc<128, 96, 4, 2, 8, 0, 2><<<dim3(3 * HDIM / 96, BDIM / 128, 2), 256, SM_BIG>>>(
                a0, a1, 3 * HDIM);
        }
        // GRU gates -> hnew fp32 + h fp16
        gru_gate_kernel<<<(int)(BH / 4 / 256), 256>>>(hprev, hnew, h_);

        // merged pe|qe: virtual N=2048, K=1024
        {
            G a{h_, h_, Wpq, b_ep, qp_t, nullptr, nullptr, nullptr,
                pe_, qe_, nullptr, HDIM, HDIM, HDIM, HDIM};
            gemm_tc<64, 64, 2, 4, 8, 3, 2><<<dim3(2 * NDIM / 64, BDIM / 64, 1), 256, SM_X>>>(
                a, a, 2 * NDIM);
        }
        // heads + reparameterized states
        float* pm_o = out + off_pm + (size_t)t * BS;
        float* ps_o = out + off_ps + (size_t)t * BS;
        float* qm_o = out + off_qm + (size_t)t * BS;
        float* qs_o = out + off_qs + (size_t)t * BS;
        {
            G a0{pe_, pe_, Wpr, b_pr, pm_o, ps_o,
                 prior_noise + (size_t)t * BS, out + off_sprior + (size_t)t * BS,
                 nullptr, nullptr, nullptr, NDIM, NDIM, NDIM, NDIM};
            G a1{qe_, qe_, Wpo, b_po, qm_o, qs_o,
                 post_noise + (size_t)t * BS, out + off_spost + (size_t)t * BS,
                 nullptr, sp_, ntNext, NDIM, NDIM, NDIM, NDIM};
            gemm_tc<32, 64, 1, 4, 4, 2, 1><<<dim3(2 * SDIM / 64, BDIM / 32, 2), 128, SM_HEAD>>>(
                a0, a1, 2 * SDIM);
        }
    }
}